// round 3
// baseline (speedup 1.0000x reference)
#include <cuda_runtime.h>
#include <cuda_bf16.h>

#define NB 64
#define NS 500
#define NH 512
#define NV 3
#define NT 500
#define GRID 128
#define NTHR 256

// ---------------- device state (scratch; allocation-free) ----------------
__device__ __align__(16) float g_apart[2][NB][1024];      // partial (unnormalized) aligns per half
__device__ float g_m[NB][2];
__device__ float g_l[NB][2];
__device__ __align__(16) float g_h1[2][NB][NH];
__device__ __align__(16) float g_c1[NB][NH];
__device__ __align__(16) float g_h2[2][NB][NH];
__device__ __align__(16) float g_c2[NB][NH];
__device__ __align__(16) float g_E[NV][4][NH];            // W_ih0[:, :512]@emb[v] + b_ih0 + b_hh0
__device__ __align__(16) float g_B2[4][NH];               // b_ih1 + b_hh1
__device__ int g_idx[NB];

// global software barrier (all GRID CTAs co-resident by construction)
__device__ unsigned g_count = 0;
__device__ volatile unsigned g_epoch = 0;

__device__ __forceinline__ void gbar() {
    __threadfence();          // make this thread's global writes visible device-wide
    __syncthreads();
    if (threadIdx.x == 0) {
        unsigned e = g_epoch;
        if (atomicAdd(&g_count, 1) == GRID - 1) {
            g_count = 0;
            __threadfence();
            g_epoch = e + 1;
        } else {
            while (g_epoch == e) { __nanosleep(64); }
        }
        __threadfence();
    }
    __syncthreads();
}

// packed fp32x2 FMA (Blackwell): 2x fp32 FMA per instruction
__device__ __forceinline__ float2 ffma2(float2 a, float2 b, float2 c) {
    float2 d;
    asm("fma.rn.f32x2 %0, %1, %2, %3;"
        : "=l"(*reinterpret_cast<unsigned long long*>(&d))
        : "l"(*reinterpret_cast<unsigned long long*>(&a)),
          "l"(*reinterpret_cast<unsigned long long*>(&b)),
          "l"(*reinterpret_cast<unsigned long long*>(&c)));
    return d;
}

__device__ __forceinline__ float sigm(float x) { return 1.f / (1.f + expf(-x)); }

// ---------------- phases ----------------

// Attention (single pass, online softmax) + logits/argmax/out for step t-1.
// CTA = (b = blk>>1, h = blk&1); h covers src rows [h*250, h*250+250).
__device__ void attn_phase(const float* __restrict__ ctx, const float* __restrict__ Wl,
                           const float* __restrict__ blv, float* __restrict__ out,
                           int t, int blk, float* smem) {
    int p = t & 1;
    int b = blk >> 1, h = blk & 1;
    int tid = threadIdx.x;
    int warp = tid >> 5, lane = tid & 31;
    float* wacc = smem;            // [8][1024]
    float* wm = smem + 8192;       // [8]
    float* wl = wm + 8;            // [8]
    float* lg = wl + 8;            // [4]

    const float* h2g = g_h2[p][b];

    // ---- logits / argmax / log_softmax output for step t-1 ----
    if (h == 0 && t > 0) {
        if (warp < 3) {
            const float* wr = Wl + warp * 512;
            float s = 0.f;
            for (int i = lane; i < 512; i += 32) s += wr[i] * h2g[i];
            for (int o = 16; o; o >>= 1) s += __shfl_xor_sync(0xffffffffu, s, o);
            if (!lane) lg[warp] = s + blv[warp];
        }
        __syncthreads();
        if (tid == 0) {
            float l0 = lg[0], l1 = lg[1], l2 = lg[2];
            int bi = 0; float bv = l0;
            if (l1 > bv) { bv = l1; bi = 1; }
            if (l2 > bv) { bv = l2; bi = 2; }
            g_idx[b] = bi;
            float lse = bv + logf(expf(l0 - bv) + expf(l1 - bv) + expf(l2 - bv));
            float* o = out + ((size_t)b * NT + (t - 1)) * 3;
            o[0] = l0 - lse; o[1] = l1 - lse; o[2] = l2 - lse;
        }
        __syncthreads();
    }
    if (t >= NT) return;   // epilogue call: logits only

    // ---- per-warp online-softmax attention over rows s = warp, warp+8, ... ----
    float4 h2v[4];
#pragma unroll
    for (int i = 0; i < 4; i++) h2v[i] = ((const float4*)h2g)[lane + 32 * i];

    float4 acc[8];
#pragma unroll
    for (int i = 0; i < 8; i++) acc[i] = make_float4(0.f, 0.f, 0.f, 0.f);
    float m = -1e30f, l = 0.f;
    int sbase = h * 250;

    for (int s = warp; s < 250; s += 8) {
        const float4* rp = (const float4*)(ctx + ((size_t)(b * NS + sbase + s)) * 1024);
        float4 cv[8];
#pragma unroll
        for (int i = 0; i < 8; i++) cv[i] = rp[lane + 32 * i];
        // score = h2 . (row[0:512] + row[512:1024])
        float sc = 0.f;
#pragma unroll
        for (int i = 0; i < 8; i++) {
            float4 hv = h2v[i & 3];
            sc += cv[i].x * hv.x + cv[i].y * hv.y + cv[i].z * hv.z + cv[i].w * hv.w;
        }
        for (int o = 16; o; o >>= 1) sc += __shfl_xor_sync(0xffffffffu, sc, o);

        float nm = fmaxf(m, sc);
        float w = __expf(sc - nm);
        if (nm > m) {
            float r = __expf(m - nm);
            l *= r;
#pragma unroll
            for (int i = 0; i < 8; i++) {
                acc[i].x *= r; acc[i].y *= r; acc[i].z *= r; acc[i].w *= r;
            }
        }
        m = nm; l += w;
#pragma unroll
        for (int i = 0; i < 8; i++) {
            acc[i].x += w * cv[i].x; acc[i].y += w * cv[i].y;
            acc[i].z += w * cv[i].z; acc[i].w += w * cv[i].w;
        }
    }
    // stash per-warp partials
#pragma unroll
    for (int i = 0; i < 8; i++) ((float4*)(wacc + warp * 1024))[lane + 32 * i] = acc[i];
    if (!lane) { wm[warp] = m; wl[warp] = l; }
    __syncthreads();

    // cross-warp combine: thread tid handles one float4 of the 1024 dims
    float M = wm[0];
#pragma unroll
    for (int w2 = 1; w2 < 8; w2++) M = fmaxf(M, wm[w2]);
    float4 o4 = make_float4(0.f, 0.f, 0.f, 0.f);
    float L = 0.f;
#pragma unroll
    for (int w2 = 0; w2 < 8; w2++) {
        float sc2 = __expf(wm[w2] - M);
        L += wl[w2] * sc2;
        float4 v = ((float4*)(wacc + w2 * 1024))[tid];
        o4.x += sc2 * v.x; o4.y += sc2 * v.y; o4.z += sc2 * v.z; o4.w += sc2 * v.w;
    }
    ((float4*)g_apart[h][b])[tid] = o4;
    if (tid == 0) { g_m[b][h] = M; g_l[b][h] = L; }
}

// gates1 GEMM [64 x 1536] x W^T -> 2048, fused align-combine + LSTM cell 1.
__device__ void lstm1_phase(const float* __restrict__ W_ih0, const float* __restrict__ W_hh0,
                            int t, int cb, float* smem) {
    int p = t & 1, q = p ^ 1;
    int tid = threadIdx.x;
    float* s0s = smem;                               // [64]
    float* s1s = smem + 64;                          // [64]
    float (*xs)[64] = (float(*)[64])(smem + 128);    // [32][64]
    float (*wsT)[16] = (float(*)[16])(smem + 2176);  // [32][16]

    if (tid < 64) {
        float m0 = g_m[tid][0], m1 = g_m[tid][1];
        float M = fmaxf(m0, m1);
        float e0 = __expf(m0 - M), e1 = __expf(m1 - M);
        float L = g_l[tid][0] * e0 + g_l[tid][1] * e1;
        s0s[tid] = e0 / L; s1s[tid] = e1 / L;
    }
    int b = tid & 63, jj = tid >> 6;
    int j0 = cb * 4 + jj;
    int vv = g_idx[b];
    float2 a01 = make_float2(g_E[vv][0][j0], g_E[vv][1][j0]);
    float2 a23 = make_float2(g_E[vv][2][j0], g_E[vv][3][j0]);

    int bq = tid >> 2;
    int kg = (tid & 3) * 8;
    int e2 = tid * 2;
    int lr = e2 >> 5, kl = e2 & 31;
    int jjr = lr >> 2, gr = lr & 3;
    int rowr = gr * 512 + cb * 4 + jjr;

    for (int kt = 0; kt < 48; kt++) {
        int kb = kt * 32;
        __syncthreads();
        {   // x tile: k<1024 -> combined align, else prev h1
            int k = kb + kg;
            if (k < 1024) {
                float s0 = s0s[bq], s1 = s1s[bq];
                const float4* a0 = (const float4*)&g_apart[0][bq][k];
                const float4* a1 = (const float4*)&g_apart[1][bq][k];
#pragma unroll
                for (int i = 0; i < 2; i++) {
                    float4 x0 = a0[i], x1 = a1[i];
                    xs[kg + i * 4 + 0][bq] = s0 * x0.x + s1 * x1.x;
                    xs[kg + i * 4 + 1][bq] = s0 * x0.y + s1 * x1.y;
                    xs[kg + i * 4 + 2][bq] = s0 * x0.z + s1 * x1.z;
                    xs[kg + i * 4 + 3][bq] = s0 * x0.w + s1 * x1.w;
                }
            } else {
                const float4* hs = (const float4*)&g_h1[p][bq][k - 1024];
#pragma unroll
                for (int i = 0; i < 2; i++) {
                    float4 x0 = hs[i];
                    xs[kg + i * 4 + 0][bq] = x0.x; xs[kg + i * 4 + 1][bq] = x0.y;
                    xs[kg + i * 4 + 2][bq] = x0.z; xs[kg + i * 4 + 3][bq] = x0.w;
                }
            }
        }
        {   // W tile (transposed into smem)
            float2 wv;
            if (kb < 1024) wv = *(const float2*)&W_ih0[(size_t)rowr * 1536 + 512 + kb + kl];
            else           wv = *(const float2*)&W_hh0[(size_t)rowr * 512 + (kb - 1024) + kl];
            wsT[kl][lr] = wv.x; wsT[kl + 1][lr] = wv.y;
        }
        __syncthreads();
#pragma unroll
        for (int k = 0; k < 32; k++) {
            float x = xs[k][b];
            float4 w4 = *(const float4*)&wsT[k][jj * 4];
            float2 xx = make_float2(x, x);
            a01 = ffma2(make_float2(w4.x, w4.y), xx, a01);
            a23 = ffma2(make_float2(w4.z, w4.w), xx, a23);
        }
    }
    float si = sigm(a01.x), sf = sigm(a01.y), so = sigm(a23.y);
    float tg = tanhf(a23.x);
    float cn = sf * g_c1[b][j0] + si * tg;
    float hn = so * tanhf(cn);
    g_c1[b][j0] = cn;
    g_h1[q][b][j0] = hn;
}

// gates2 GEMM [64 x 1024] -> 2048 + LSTM cell 2.
__device__ void lstm2_phase(const float* __restrict__ W_ih1, const float* __restrict__ W_hh1,
                            int t, int cb, float* smem) {
    int p = t & 1, q = p ^ 1;
    int tid = threadIdx.x;
    float (*xs)[64] = (float(*)[64])(smem + 128);
    float (*wsT)[16] = (float(*)[16])(smem + 2176);

    int b = tid & 63, jj = tid >> 6;
    int j0 = cb * 4 + jj;
    float2 a01 = make_float2(g_B2[0][j0], g_B2[1][j0]);
    float2 a23 = make_float2(g_B2[2][j0], g_B2[3][j0]);

    int bq = tid >> 2;
    int kg = (tid & 3) * 8;
    int e2 = tid * 2;
    int lr = e2 >> 5, kl = e2 & 31;
    int jjr = lr >> 2, gr = lr & 3;
    int rowr = gr * 512 + cb * 4 + jjr;

    for (int kt = 0; kt < 32; kt++) {
        int kb = kt * 32;
        __syncthreads();
        {
            int k = kb + kg;
            const float4* src = (k < 512) ? (const float4*)&g_h1[q][bq][k]
                                          : (const float4*)&g_h2[p][bq][k - 512];
#pragma unroll
            for (int i = 0; i < 2; i++) {
                float4 x0 = src[i];
                xs[kg + i * 4 + 0][bq] = x0.x; xs[kg + i * 4 + 1][bq] = x0.y;
                xs[kg + i * 4 + 2][bq] = x0.z; xs[kg + i * 4 + 3][bq] = x0.w;
            }
        }
        {
            float2 wv;
            if (kb < 512) wv = *(const float2*)&W_ih1[(size_t)rowr * 512 + kb + kl];
            else          wv = *(const float2*)&W_hh1[(size_t)rowr * 512 + (kb - 512) + kl];
            wsT[kl][lr] = wv.x; wsT[kl + 1][lr] = wv.y;
        }
        __syncthreads();
#pragma unroll
        for (int k = 0; k < 32; k++) {
            float x = xs[k][b];
            float4 w4 = *(const float4*)&wsT[k][jj * 4];
            float2 xx = make_float2(x, x);
            a01 = ffma2(make_float2(w4.x, w4.y), xx, a01);
            a23 = ffma2(make_float2(w4.z, w4.w), xx, a23);
        }
    }
    float si = sigm(a01.x), sf = sigm(a01.y), so = sigm(a23.y);
    float tg = tanhf(a23.x);
    float cn = sf * g_c2[b][j0] + si * tg;
    float hn = so * tanhf(cn);
    g_c2[b][j0] = cn;
    g_h2[q][b][j0] = hn;
}

// ---------------- the persistent kernel ----------------
__global__ void __launch_bounds__(NTHR, 1)
k_persist(const float* __restrict__ ctx, const int* __restrict__ tgt,
          const float* __restrict__ h1_0, const float* __restrict__ c1_0,
          const float* __restrict__ h2_0, const float* __restrict__ c2_0,
          const float* __restrict__ emb,
          const float* __restrict__ W_ih0, const float* __restrict__ W_hh0,
          const float* __restrict__ b_ih0, const float* __restrict__ b_hh0,
          const float* __restrict__ W_ih1, const float* __restrict__ W_hh1,
          const float* __restrict__ b_ih1, const float* __restrict__ b_hh1,
          const float* __restrict__ Wl, const float* __restrict__ blv,
          float* __restrict__ out, int out_size) {
    __shared__ __align__(16) float smem[8448];   // 33 KB, unioned across phases
    int blk = blockIdx.x;
    int tid = threadIdx.x;
    int warp = tid >> 5, lane = tid & 31;

    // ---- setup ----
    {
        int gi = blk * NTHR + tid;       // 0..32767 == NB*NH
        ((float*)g_h1[0])[gi] = h1_0[gi];
        ((float*)g_c1)[gi]    = c1_0[gi];
        ((float*)g_h2[0])[gi] = h2_0[gi];
        ((float*)g_c2)[gi]    = c2_0[gi];
        if (gi < 4 * NH) ((float*)g_B2)[gi] = b_ih1[gi] + b_hh1[gi];
        if (blk == 0 && tid < NB) g_idx[tid] = tgt[tid * NT];
        // E table: 6144 warp-dots over 1024 warps
        for (int r = blk * 8 + warp; r < NV * 2048; r += GRID * 8) {
            int v = r / 2048, row = r % 2048;
            const float* wr = W_ih0 + (size_t)row * 1536;
            const float* ev = emb + v * 512;
            float s = 0.f;
            for (int i = lane; i < 512; i += 32) s += wr[i] * ev[i];
            for (int o = 16; o; o >>= 1) s += __shfl_xor_sync(0xffffffffu, s, o);
            if (!lane) g_E[v][row >> 9][row & 511] = s + b_ih0[row] + b_hh0[row];
        }
    }
    gbar();

    // ---- decode loop ----
    for (int t = 0; t <= NT; t++) {
        attn_phase(ctx, Wl, blv, out, t, blk, smem);
        if (t == NT) break;
        gbar();
        lstm1_phase(W_ih0, W_hh0, t, blk, smem);
        gbar();
        lstm2_phase(W_ih1, W_hh1, t, blk, smem);
        gbar();
    }

    // ---- append targets (as float) if the output buffer carries them ----
    if (out_size >= NB * NT * NV + NB * NT) {
        int i = blk * NTHR + tid;
        if (i < NB * NT) out[NB * NT * NV + i] = (float)tgt[i];
    }
}

// ---------------- launch ----------------
extern "C" void kernel_launch(void* const* d_in, const int* in_sizes, int n_in,
                              void* d_out, int out_size) {
    int off = (n_in >= 18) ? 0 : -1;   // tolerate teacher_ratio being dropped
    const float* ctx   = (const float*)d_in[0];
    const int*   tgt   = (const int*)d_in[1];
    const float* h1_0  = (const float*)d_in[3 + off];
    const float* c1_0  = (const float*)d_in[4 + off];
    const float* h2_0  = (const float*)d_in[5 + off];
    const float* c2_0  = (const float*)d_in[6 + off];
    const float* emb   = (const float*)d_in[7 + off];
    const float* W_ih0 = (const float*)d_in[8 + off];
    const float* W_hh0 = (const float*)d_in[9 + off];
    const float* b_ih0 = (const float*)d_in[10 + off];
    const float* b_hh0 = (const float*)d_in[11 + off];
    const float* W_ih1 = (const float*)d_in[12 + off];
    const float* W_hh1 = (const float*)d_in[13 + off];
    const float* b_ih1 = (const float*)d_in[14 + off];
    const float* b_hh1 = (const float*)d_in[15 + off];
    const float* Wl    = (const float*)d_in[16 + off];
    const float* bl    = (const float*)d_in[17 + off];
    float* out = (float*)d_out;

    k_persist<<<GRID, NTHR>>>(ctx, tgt, h1_0, c1_0, h2_0, c2_0, emb,
                              W_ih0, W_hh0, b_ih0, b_hh0,
                              W_ih1, W_hh1, b_ih1, b_hh1,
                              Wl, bl, out, out_size);
}